// round 2
// baseline (speedup 1.0000x reference)
#include <cuda_runtime.h>

// Problem constants
#define B_    64
#define T_    1000
#define INF   512
#define OUTF  512

// Scratch for cur_in laid out (b, t, o) — 131 MB static device global (allowed).
__device__ float g_cur[(size_t)B_ * T_ * OUTF];

// ---------------------------------------------------------------------------
// Stage 1: C[m][n] = sum_k A[m][k] * W[n][k]   (A: 64000x512, W: 512x512, NT GEMM)
// 128x128x16 tiles, 256 threads, 8x8 microtile, double-buffered smem, fp32.
// ---------------------------------------------------------------------------
__global__ __launch_bounds__(256, 2) void gemm_nt_kernel(
    const float* __restrict__ A, const float* __restrict__ W,
    float* __restrict__ C)
{
    const int K = INF;
    const int N = OUTF;

    __shared__ float As[2][16][132];
    __shared__ float Bs[2][16][132];

    const int tid = threadIdx.x;
    const int bm  = blockIdx.x * 128;
    const int bn  = blockIdx.y * 128;
    const int tx  = tid & 15;   // n dir
    const int ty  = tid >> 4;   // m dir

    float acc[8][8];
#pragma unroll
    for (int i = 0; i < 8; ++i)
#pragma unroll
        for (int j = 0; j < 8; ++j) acc[i][j] = 0.f;

    float4 pa[2], pb[2];

    // prologue: load k-tile 0
#pragma unroll
    for (int s = 0; s < 2; ++s) {
        int lin = tid + s * 256;
        int row = lin >> 2;
        int kc  = lin & 3;
        pa[s] = *(const float4*)&A[(size_t)(bm + row) * K + kc * 4];
        pb[s] = *(const float4*)&W[(size_t)(bn + row) * K + kc * 4];
    }
#pragma unroll
    for (int s = 0; s < 2; ++s) {
        int lin = tid + s * 256;
        int row = lin >> 2;
        int kc  = lin & 3;
        As[0][kc * 4 + 0][row] = pa[s].x;
        As[0][kc * 4 + 1][row] = pa[s].y;
        As[0][kc * 4 + 2][row] = pa[s].z;
        As[0][kc * 4 + 3][row] = pa[s].w;
        Bs[0][kc * 4 + 0][row] = pb[s].x;
        Bs[0][kc * 4 + 1][row] = pb[s].y;
        Bs[0][kc * 4 + 2][row] = pb[s].z;
        Bs[0][kc * 4 + 3][row] = pb[s].w;
    }
    __syncthreads();

    const int NK = K / 16;  // 32
    for (int kt = 0; kt < NK; ++kt) {
        const int cur = kt & 1;
        if (kt + 1 < NK) {
            const int k0 = (kt + 1) * 16;
#pragma unroll
            for (int s = 0; s < 2; ++s) {
                int lin = tid + s * 256;
                int row = lin >> 2;
                int kc  = lin & 3;
                pa[s] = *(const float4*)&A[(size_t)(bm + row) * K + k0 + kc * 4];
                pb[s] = *(const float4*)&W[(size_t)(bn + row) * K + k0 + kc * 4];
            }
        }
#pragma unroll
        for (int kk = 0; kk < 16; ++kk) {
            float4 a0 = *(const float4*)&As[cur][kk][ty * 8];
            float4 a1 = *(const float4*)&As[cur][kk][ty * 8 + 4];
            float4 b0 = *(const float4*)&Bs[cur][kk][tx * 8];
            float4 b1 = *(const float4*)&Bs[cur][kk][tx * 8 + 4];
            float av[8] = {a0.x, a0.y, a0.z, a0.w, a1.x, a1.y, a1.z, a1.w};
            float bv[8] = {b0.x, b0.y, b0.z, b0.w, b1.x, b1.y, b1.z, b1.w};
#pragma unroll
            for (int i = 0; i < 8; ++i)
#pragma unroll
                for (int j = 0; j < 8; ++j)
                    acc[i][j] += av[i] * bv[j];
        }
        if (kt + 1 < NK) {
            const int nxt = cur ^ 1;
#pragma unroll
            for (int s = 0; s < 2; ++s) {
                int lin = tid + s * 256;
                int row = lin >> 2;
                int kc  = lin & 3;
                As[nxt][kc * 4 + 0][row] = pa[s].x;
                As[nxt][kc * 4 + 1][row] = pa[s].y;
                As[nxt][kc * 4 + 2][row] = pa[s].z;
                As[nxt][kc * 4 + 3][row] = pa[s].w;
                Bs[nxt][kc * 4 + 0][row] = pb[s].x;
                Bs[nxt][kc * 4 + 1][row] = pb[s].y;
                Bs[nxt][kc * 4 + 2][row] = pb[s].z;
                Bs[nxt][kc * 4 + 3][row] = pb[s].w;
            }
            __syncthreads();
        }
    }

    // epilogue: vectorized store
#pragma unroll
    for (int i = 0; i < 8; ++i) {
        float4 c0 = make_float4(acc[i][0], acc[i][1], acc[i][2], acc[i][3]);
        float4 c1 = make_float4(acc[i][4], acc[i][5], acc[i][6], acc[i][7]);
        size_t off = (size_t)(bm + ty * 8 + i) * N + bn + tx * 8;
        *(float4*)&C[off]     = c0;
        *(float4*)&C[off + 4] = c1;
    }
}

// ---------------------------------------------------------------------------
// Stage 2: sequential ALIF scan. One CTA per batch, one thread per neuron.
// State (v, z, b) in registers; recurrent coupling via smem spike exchange.
// Output layout: [zs (B,T,OUT)] then [states (3, B, T+1, OUT)].
// ---------------------------------------------------------------------------
__global__ __launch_bounds__(512, 1) void alif_scan_kernel(
    const float* __restrict__ cur_in,   // (b, t, o)
    const float* __restrict__ bias,
    const float* __restrict__ R,        // (OUT, OUT) row-major; rec[o] = sum_j z[j]*R[o][j]
    const float* __restrict__ beta,
    const float* __restrict__ beta2,
    const float* __restrict__ decay_v,
    const float* __restrict__ decay_b,
    float* __restrict__ out)
{
    const int b = blockIdx.x;
    const int o = threadIdx.x;

    __shared__ float zsm[OUTF];

    const float Bias  = bias[o];
    const float Beta  = beta[o];
    const float Beta2 = beta2[o];
    const float Dv    = decay_v[o];
    const float Db    = decay_b[o];
    const float omDv  = 1.f - Dv;
    const float omDb  = 1.f - Db;

    float v = 0.f, z = 0.f, ba = 0.f;

    const size_t SB = (size_t)B_ * T_ * OUTF;  // start of states in out
    float* zs  = out + ((size_t)b * T_) * OUTF + o;
    float* vs  = out + SB + (((size_t)0 * B_ + b) * (T_ + 1) + 1) * (size_t)OUTF + o;
    float* zs2 = out + SB + (((size_t)1 * B_ + b) * (T_ + 1) + 1) * (size_t)OUTF + o;
    float* bs  = out + SB + (((size_t)2 * B_ + b) * (T_ + 1) + 1) * (size_t)OUTF + o;

    // zero the t=0 pad of all three state tensors
    out[SB + (((size_t)0 * B_ + b) * (T_ + 1)) * OUTF + o] = 0.f;
    out[SB + (((size_t)1 * B_ + b) * (T_ + 1)) * OUTF + o] = 0.f;
    out[SB + (((size_t)2 * B_ + b) * (T_ + 1)) * OUTF + o] = 0.f;

    const float* cin = cur_in + ((size_t)b * T_) * OUTF + o;

    float p0 = cin[(size_t)0 * OUTF];
    float p1 = cin[(size_t)1 * OUTF];
    float p2 = cin[(size_t)2 * OUTF];
    float p3 = cin[(size_t)3 * OUTF];

#define ALIF_STEP(tt, curval)                                                  \
    do {                                                                       \
        zsm[o] = z;                                                            \
        int cnt = __syncthreads_count(z != 0.f);                               \
        float rec = 0.f;                                                       \
        if (cnt) {                                                             \
            for (int j = 0; j < OUTF; ++j) {                                   \
                float zj = zsm[j];                                             \
                if (zj != 0.f) rec += R[(size_t)o * OUTF + j];                 \
            }                                                                  \
            __syncthreads();                                                   \
        }                                                                      \
        v *= (1.f - z);                                                        \
        float c = (curval) + Bias + rec;                                       \
        v = Dv * v + omDv * (c - ba);                                          \
        z = (v >= 1.0f) ? 1.f : 0.f;                                           \
        ba = Db * ba + omDb * (Beta * v + Beta2 * z);                          \
        zs[(size_t)(tt) * OUTF]  = z;                                          \
        vs[(size_t)(tt) * OUTF]  = v;                                          \
        zs2[(size_t)(tt) * OUTF] = z;                                          \
        bs[(size_t)(tt) * OUTF]  = ba;                                         \
    } while (0)

    for (int t = 0; t < T_; t += 4) {
        float n0 = 0.f, n1 = 0.f, n2 = 0.f, n3 = 0.f;
        if (t + 4 < T_) {  // prefetch 4 steps ahead (MLP=4)
            n0 = cin[(size_t)(t + 4) * OUTF];
            n1 = cin[(size_t)(t + 5) * OUTF];
            n2 = cin[(size_t)(t + 6) * OUTF];
            n3 = cin[(size_t)(t + 7) * OUTF];
        }
        ALIF_STEP(t + 0, p0);
        ALIF_STEP(t + 1, p1);
        ALIF_STEP(t + 2, p2);
        ALIF_STEP(t + 3, p3);
        p0 = n0; p1 = n1; p2 = n2; p3 = n3;
    }
#undef ALIF_STEP
}

// ---------------------------------------------------------------------------
// Launch
// ---------------------------------------------------------------------------
extern "C" void kernel_launch(void* const* d_in, const int* in_sizes, int n_in,
                              void* d_out, int out_size)
{
    const float* x     = (const float*)d_in[0];  // (B, T, IN)
    const float* w     = (const float*)d_in[1];  // (OUT, IN)
    const float* bias  = (const float*)d_in[2];  // (OUT,)
    const float* R     = (const float*)d_in[3];  // (OUT, OUT)
    const float* beta  = (const float*)d_in[4];
    const float* beta2 = (const float*)d_in[5];
    const float* dv    = (const float*)d_in[6];
    const float* db    = (const float*)d_in[7];
    float* out = (float*)d_out;

    float* cur = nullptr;
    cudaGetSymbolAddress((void**)&cur, g_cur);

    dim3 grid((B_ * T_) / 128, OUTF / 128);  // (500, 4)
    gemm_nt_kernel<<<grid, 256>>>(x, w, cur);
    alif_scan_kernel<<<B_, OUTF>>>(cur, bias, R, beta, beta2, dv, db, out);
}

// round 4
// speedup vs baseline: 1.5872x; 1.5872x over previous
#include <cuda_runtime.h>
#include <cuda_bf16.h>
#include <cstdint>

// Problem constants
#define B_    64
#define T_    1000
#define INF   512
#define OUTF  512

// Scratch (static __device__ allocations are allowed)
__device__ float         g_cur[(size_t)B_ * T_ * OUTF];          // 131 MB
__device__ __nv_bfloat16 g_xh[(size_t)B_ * T_ * INF];            // 65.5 MB
__device__ __nv_bfloat16 g_xl[(size_t)B_ * T_ * INF];
__device__ __nv_bfloat16 g_wh[(size_t)OUTF * INF];
__device__ __nv_bfloat16 g_wl[(size_t)OUTF * INF];

// ---------------------------------------------------------------------------
// PTX helpers (target-generic: ldmatrix / mma.sync / cp.async only)
// ---------------------------------------------------------------------------
__device__ __forceinline__ uint32_t smem_u32(const void* p) {
    uint32_t a;
    asm("{ .reg .u64 t; cvta.to.shared.u64 t, %1; cvt.u32.u64 %0, t; }"
        : "=r"(a) : "l"(p));
    return a;
}

__device__ __forceinline__ void ldsm_x4(uint32_t* r, uint32_t addr) {
    asm volatile("ldmatrix.sync.aligned.m8n8.x4.shared.b16 {%0,%1,%2,%3}, [%4];"
                 : "=r"(r[0]), "=r"(r[1]), "=r"(r[2]), "=r"(r[3]) : "r"(addr));
}

__device__ __forceinline__ void mma16816(float* d, const uint32_t* a,
                                         const uint32_t* b) {
    asm volatile(
        "mma.sync.aligned.m16n8k16.row.col.f32.bf16.bf16.f32 "
        "{%0,%1,%2,%3}, {%4,%5,%6,%7}, {%8,%9}, {%0,%1,%2,%3};"
        : "+f"(d[0]), "+f"(d[1]), "+f"(d[2]), "+f"(d[3])
        : "r"(a[0]), "r"(a[1]), "r"(a[2]), "r"(a[3]), "r"(b[0]), "r"(b[1]));
}

#define CP_ASYNC16(dst, src)                                                  \
    asm volatile("cp.async.cg.shared.global [%0], [%1], 16;" :: "r"(dst), "l"(src))
#define CP_COMMIT() asm volatile("cp.async.commit_group;" ::: "memory")
#define CP_WAIT1()  asm volatile("cp.async.wait_group 1;" ::: "memory")

// ---------------------------------------------------------------------------
// Stage 0: fp32 -> (bf16 hi, bf16 lo) split, vectorized 4 elems/thread
// ---------------------------------------------------------------------------
__global__ void split_kernel(const float* __restrict__ src,
                             __nv_bfloat16* __restrict__ hi,
                             __nv_bfloat16* __restrict__ lo, int n4)
{
    int i = blockIdx.x * blockDim.x + threadIdx.x;
    if (i >= n4) return;
    float4 v = ((const float4*)src)[i];
    __nv_bfloat16 h0 = __float2bfloat16_rn(v.x);
    __nv_bfloat16 h1 = __float2bfloat16_rn(v.y);
    __nv_bfloat16 h2 = __float2bfloat16_rn(v.z);
    __nv_bfloat16 h3 = __float2bfloat16_rn(v.w);
    __nv_bfloat16 l0 = __float2bfloat16_rn(v.x - __bfloat162float(h0));
    __nv_bfloat16 l1 = __float2bfloat16_rn(v.y - __bfloat162float(h1));
    __nv_bfloat16 l2 = __float2bfloat16_rn(v.z - __bfloat162float(h2));
    __nv_bfloat16 l3 = __float2bfloat16_rn(v.w - __bfloat162float(h3));
    uint2 hv, lv;
    hv.x = (uint32_t)__bfloat16_as_ushort(h0) | ((uint32_t)__bfloat16_as_ushort(h1) << 16);
    hv.y = (uint32_t)__bfloat16_as_ushort(h2) | ((uint32_t)__bfloat16_as_ushort(h3) << 16);
    lv.x = (uint32_t)__bfloat16_as_ushort(l0) | ((uint32_t)__bfloat16_as_ushort(l1) << 16);
    lv.y = (uint32_t)__bfloat16_as_ushort(l2) | ((uint32_t)__bfloat16_as_ushort(l3) << 16);
    ((uint2*)hi)[i] = hv;
    ((uint2*)lo)[i] = lv;
}

// ---------------------------------------------------------------------------
// Stage 1: HMMA bf16-split GEMM.  C[m][n] = sum_k A[m][k]*W[n][k]
// BM=128 BN=128 BK=32, 256 thr (8 warps, 2x4 grid of 64x32 warp tiles),
// 3-stage cp.async pipeline, row stride 80 B (64 B data + 16 B pad).
// ---------------------------------------------------------------------------
#define BM 128
#define BN 128
#define BK 32
#define NSTAGE 3
#define ROWB 80                       // padded row stride in bytes
#define STAGE_BYTES (4 * BM * ROWB)   // Ah, Al, Bh, Bl tiles: 40960
#define OFF_AH 0
#define OFF_AL (BM * ROWB)
#define OFF_BH (2 * BM * ROWB)
#define OFF_BL (3 * BM * ROWB)
#define SM_TOT (NSTAGE * STAGE_BYTES) // 122880

__global__ __launch_bounds__(256, 1) void gemm_hmma_kernel(
    const __nv_bfloat16* __restrict__ xh, const __nv_bfloat16* __restrict__ xl,
    const __nv_bfloat16* __restrict__ wh, const __nv_bfloat16* __restrict__ wl,
    float* __restrict__ C)
{
    extern __shared__ char smem[];
    const uint32_t sb = smem_u32(smem);
    const int tid  = threadIdx.x;
    const int wid  = tid >> 5;
    const int lane = tid & 31;
    const int bm = blockIdx.x * BM;
    const int bn = blockIdx.y * BN;
    const int wm = (wid >> 2) * 64;   // warp m offset in tile
    const int wn = (wid & 3) * 32;    // warp n offset in tile

    // per-thread load assignment: 2 segments of 16B per array per stage
    const int r0 = tid >> 2;          // row 0..63  (segment tid)
    const int c0 = tid & 3;           // 16B col 0..3
    const int r1 = (tid + 256) >> 2;  // row 64..127
    const int c1 = c0;

    float acc[4][4][4];
#pragma unroll
    for (int i = 0; i < 4; ++i)
#pragma unroll
        for (int j = 0; j < 4; ++j)
#pragma unroll
            for (int k = 0; k < 4; ++k) acc[i][j][k] = 0.f;

    // ldmatrix address precompute (byte offsets within a stage)
    // A: row = wm + mi*16 + (lane&15), colByte = (lane>>4)*16 + ks*32
    const int a_row = (lane & 15);
    const int a_cb  = (lane >> 4) * 16;
    // B: g = lane>>3, r8 = lane&7; row = wn + nj*16 + ((g&2)?8:0)+r8; cb=(g&1)*16
    const int b_g   = lane >> 3;
    const int b_row = ((b_g & 2) ? 8 : 0) + (lane & 7);
    const int b_cb  = (b_g & 1) * 16;

#define LOAD_STAGE(st, kt)                                                    \
    do {                                                                      \
        const int koff = (kt) * BK;                                           \
        uint32_t base = sb + (st) * STAGE_BYTES;                              \
        CP_ASYNC16(base + OFF_AH + r0 * ROWB + c0 * 16,                       \
                   xh + (size_t)(bm + r0) * INF + koff + c0 * 8);             \
        CP_ASYNC16(base + OFF_AH + r1 * ROWB + c1 * 16,                       \
                   xh + (size_t)(bm + r1) * INF + koff + c1 * 8);             \
        CP_ASYNC16(base + OFF_AL + r0 * ROWB + c0 * 16,                       \
                   xl + (size_t)(bm + r0) * INF + koff + c0 * 8);             \
        CP_ASYNC16(base + OFF_AL + r1 * ROWB + c1 * 16,                       \
                   xl + (size_t)(bm + r1) * INF + koff + c1 * 8);             \
        CP_ASYNC16(base + OFF_BH + r0 * ROWB + c0 * 16,                       \
                   wh + (size_t)(bn + r0) * INF + koff + c0 * 8);             \
        CP_ASYNC16(base + OFF_BH + r1 * ROWB + c1 * 16,                       \
                   wh + (size_t)(bn + r1) * INF + koff + c1 * 8);             \
        CP_ASYNC16(base + OFF_BL + r0 * ROWB + c0 * 16,                       \
                   wl + (size_t)(bn + r0) * INF + koff + c0 * 8);             \
        CP_ASYNC16(base + OFF_BL + r1 * ROWB + c1 * 16,                       \
                   wl + (size_t)(bn + r1) * INF + koff + c1 * 8);             \
    } while (0)

    // prologue: stages 0 and 1
    LOAD_STAGE(0, 0);
    CP_COMMIT();
    LOAD_STAGE(1, 1);
    CP_COMMIT();

    const int KT = INF / BK;  // 16
    for (int kt = 0; kt < KT; ++kt) {
        const int st = kt % NSTAGE;
        CP_WAIT1();
        __syncthreads();

        if (kt + 2 < KT) LOAD_STAGE((kt + 2) % NSTAGE, kt + 2);
        CP_COMMIT();

        const uint32_t base = sb + st * STAGE_BYTES;
#pragma unroll
        for (int ks = 0; ks < 2; ++ks) {   // two k16 steps per 32-chunk
            uint32_t ah[4][4], al[4][4], bh[4][2], bl[4][2];
#pragma unroll
            for (int mi = 0; mi < 4; ++mi) {
                uint32_t ra = base + OFF_AH +
                              (uint32_t)(wm + mi * 16 + a_row) * ROWB +
                              ks * 32 + a_cb;
                ldsm_x4(ah[mi], ra);
                ldsm_x4(al[mi], ra + (OFF_AL - OFF_AH));
            }
#pragma unroll
            for (int nj = 0; nj < 2; ++nj) {
                uint32_t rb = base + OFF_BH +
                              (uint32_t)(wn + nj * 16 + b_row) * ROWB +
                              ks * 32 + b_cb;
                uint32_t t[4];
                ldsm_x4(t, rb);
                bh[2 * nj][0] = t[0]; bh[2 * nj][1] = t[1];
                bh[2 * nj + 1][0] = t[2]; bh[2 * nj + 1][1] = t[3];
                ldsm_x4(t, rb + (OFF_BL - OFF_BH));
                bl[2 * nj][0] = t[0]; bl[2 * nj][1] = t[1];
                bl[2 * nj + 1][0] = t[2]; bl[2 * nj + 1][1] = t[3];
            }
#pragma unroll
            for (int mi = 0; mi < 4; ++mi)
#pragma unroll
                for (int ni = 0; ni < 4; ++ni) {
                    mma16816(acc[mi][ni], ah[mi], bh[ni]);
                    mma16816(acc[mi][ni], ah[mi], bl[ni]);
                    mma16816(acc[mi][ni], al[mi], bh[ni]);
                }
        }
    }

    // epilogue: frag -> global
    const int er = lane >> 2;        // 0..7
    const int ec = (lane & 3) * 2;   // 0,2,4,6
#pragma unroll
    for (int mi = 0; mi < 4; ++mi) {
#pragma unroll
        for (int ni = 0; ni < 4; ++ni) {
            size_t row0 = (size_t)(bm + wm + mi * 16 + er);
            size_t col  = (size_t)(bn + wn + ni * 8 + ec);
            float2 v0 = make_float2(acc[mi][ni][0], acc[mi][ni][1]);
            float2 v1 = make_float2(acc[mi][ni][2], acc[mi][ni][3]);
            *(float2*)&C[row0 * OUTF + col]       = v0;
            *(float2*)&C[(row0 + 8) * OUTF + col] = v1;
        }
    }
}

// ---------------------------------------------------------------------------
// Stage 2: sequential ALIF scan (unchanged, known-good, 205us)
// ---------------------------------------------------------------------------
__global__ __launch_bounds__(512, 1) void alif_scan_kernel(
    const float* __restrict__ cur_in,
    const float* __restrict__ bias,
    const float* __restrict__ R,
    const float* __restrict__ beta,
    const float* __restrict__ beta2,
    const float* __restrict__ decay_v,
    const float* __restrict__ decay_b,
    float* __restrict__ out)
{
    const int b = blockIdx.x;
    const int o = threadIdx.x;

    __shared__ float zsm[OUTF];

    const float Bias  = bias[o];
    const float Beta  = beta[o];
    const float Beta2 = beta2[o];
    const float Dv    = decay_v[o];
    const float Db    = decay_b[o];
    const float omDv  = 1.f - Dv;
    const float omDb  = 1.f - Db;

    float v = 0.f, z = 0.f, ba = 0.f;

    const size_t SB = (size_t)B_ * T_ * OUTF;
    float* zs  = out + ((size_t)b * T_) * OUTF + o;
    float* vs  = out + SB + (((size_t)0 * B_ + b) * (T_ + 1) + 1) * (size_t)OUTF + o;
    float* zs2 = out + SB + (((size_t)1 * B_ + b) * (T_ + 1) + 1) * (size_t)OUTF + o;
    float* bs  = out + SB + (((size_t)2 * B_ + b) * (T_ + 1) + 1) * (size_t)OUTF + o;

    out[SB + (((size_t)0 * B_ + b) * (T_ + 1)) * OUTF + o] = 0.f;
    out[SB + (((size_t)1 * B_ + b) * (T_ + 1)) * OUTF + o] = 0.f;
    out[SB + (((size_t)2 * B_ + b) * (T_ + 1)) * OUTF + o] = 0.f;

    const float* cin = cur_in + ((size_t)b * T_) * OUTF + o;

    float p0 = cin[(size_t)0 * OUTF];
    float p1 = cin[(size_t)1 * OUTF];
    float p2 = cin[(size_t)2 * OUTF];
    float p3 = cin[(size_t)3 * OUTF];

#define ALIF_STEP(tt, curval)                                                  \
    do {                                                                       \
        zsm[o] = z;                                                            \
        int cnt = __syncthreads_count(z != 0.f);                               \
        float rec = 0.f;                                                       \
        if (cnt) {                                                             \
            for (int j = 0; j < OUTF; ++j) {                                   \
                float zj = zsm[j];                                             \
                if (zj != 0.f) rec += R[(size_t)o * OUTF + j];                 \
            }                                                                  \
            __syncthreads();                                                   \
        }                                                                      \
        v *= (1.f - z);                                                        \
        float c = (curval) + Bias + rec;                                       \
        v = Dv * v + omDv * (c - ba);                                          \
        z = (v >= 1.0f) ? 1.f : 0.f;                                           \
        ba = Db * ba + omDb * (Beta * v + Beta2 * z);                          \
        zs[(size_t)(tt) * OUTF]  = z;                                          \
        vs[(size_t)(tt) * OUTF]  = v;                                          \
        zs2[(size_t)(tt) * OUTF] = z;                                          \
        bs[(size_t)(tt) * OUTF]  = ba;                                         \
    } while (0)

    for (int t = 0; t < T_; t += 4) {
        float n0 = 0.f, n1 = 0.f, n2 = 0.f, n3 = 0.f;
        if (t + 4 < T_) {
            n0 = cin[(size_t)(t + 4) * OUTF];
            n1 = cin[(size_t)(t + 5) * OUTF];
            n2 = cin[(size_t)(t + 6) * OUTF];
            n3 = cin[(size_t)(t + 7) * OUTF];
        }
        ALIF_STEP(t + 0, p0);
        ALIF_STEP(t + 1, p1);
        ALIF_STEP(t + 2, p2);
        ALIF_STEP(t + 3, p3);
        p0 = n0; p1 = n1; p2 = n2; p3 = n3;
    }
#undef ALIF_STEP
}

// ---------------------------------------------------------------------------
// Launch
// ---------------------------------------------------------------------------
extern "C" void kernel_launch(void* const* d_in, const int* in_sizes, int n_in,
                              void* d_out, int out_size)
{
    const float* x     = (const float*)d_in[0];
    const float* w     = (const float*)d_in[1];
    const float* bias  = (const float*)d_in[2];
    const float* R     = (const float*)d_in[3];
    const float* beta  = (const float*)d_in[4];
    const float* beta2 = (const float*)d_in[5];
    const float* dv    = (const float*)d_in[6];
    const float* db    = (const float*)d_in[7];
    float* out = (float*)d_out;

    float* cur = nullptr;
    __nv_bfloat16 *xh, *xl, *wh, *wl;
    cudaGetSymbolAddress((void**)&cur, g_cur);
    cudaGetSymbolAddress((void**)&xh, g_xh);
    cudaGetSymbolAddress((void**)&xl, g_xl);
    cudaGetSymbolAddress((void**)&wh, g_wh);
    cudaGetSymbolAddress((void**)&wl, g_wl);

    cudaFuncSetAttribute(gemm_hmma_kernel,
                         cudaFuncAttributeMaxDynamicSharedMemorySize, SM_TOT);

    const int n4x = (B_ * T_ * INF) / 4;   // 8,192,000
    const int n4w = (OUTF * INF) / 4;      // 65,536
    split_kernel<<<(n4x + 255) / 256, 256>>>(x, xh, xl, n4x);
    split_kernel<<<(n4w + 255) / 256, 256>>>(w, wh, wl, n4w);

    dim3 grid((B_ * T_) / BM, OUTF / BN);  // (500, 4)
    gemm_hmma_kernel<<<grid, 256, SM_TOT>>>(xh, xl, wh, wl, cur);
    alif_scan_kernel<<<B_, OUTF>>>(cur, bias, R, beta, beta2, dv, db, out);
}